// round 15
// baseline (speedup 1.0000x reference)
#include <cuda_runtime.h>
#include <cstdint>

// Embedding gather via async bulk DMA: out[r,:] = weight[ids[r],:]
// weight: [50257, 1024] fp32 (4KB/row), ids: [32768] int32, out: [32768,1024] fp32
//
// R14: every LDG/STG variant plateaus at ~188MB @ ~69% of HBM spec — the
// DRAM stream is 128B-granular interleaved r/w. This version moves whole
// 4KB rows with cp.async.bulk (global->smem->global), giving the memory
// controller page-sized sequential bursts.
//   - 8-stage 4KB SMEM ring per CTA, mbarrier-completed loads
//   - single issuing thread per CTA (work is DMA, not instruction issue)
//   - loads run LOOKAHEAD=6 ahead; stage reuse gated by wait_group.read 2
// 1024 CTAs x 32 rows = 32768 rows.

#define STAGES     8
#define LOOKAHEAD  6
#define ROWS_PER_CTA 32
#define ROW_BYTES  4096

__device__ __forceinline__ uint32_t smem_u32(const void* p) {
    uint32_t a;
    asm("{ .reg .u64 t; cvta.to.shared.u64 t, %1; cvt.u32.u64 %0, t; }"
        : "=r"(a) : "l"(p));
    return a;
}

__global__ void __launch_bounds__(32)
embed_bulk_kernel(const float* __restrict__ weight,
                  const int* __restrict__ ids,
                  float* __restrict__ out,
                  int n_rows)
{
    __shared__ alignas(128) char buf[STAGES][ROW_BYTES];
    __shared__ alignas(8)  uint64_t mbar[STAGES];

    if (threadIdx.x != 0) return;   // DMA pipeline needs one issuing thread

    uint32_t mb[STAGES], sb[STAGES];
#pragma unroll
    for (int s = 0; s < STAGES; s++) {
        mb[s] = smem_u32(&mbar[s]);
        sb[s] = smem_u32(&buf[s][0]);
        asm volatile("mbarrier.init.shared.b64 [%0], 1;" :: "r"(mb[s]) : "memory");
    }
    // order generic-proxy mbarrier init before async-proxy use
    asm volatile("fence.proxy.async.shared::cta;" ::: "memory");

    const int row0 = blockIdx.x * ROWS_PER_CTA;

    // prologue: issue LOOKAHEAD row loads
#pragma unroll
    for (int j = 0; j < LOOKAHEAD; j++) {
        int idx = ids[row0 + j];
        const char* src = (const char*)weight + (size_t)idx * ROW_BYTES;
        uint32_t m = mb[j];
        asm volatile("mbarrier.arrive.expect_tx.shared.b64 _, [%0], %1;"
                     :: "r"(m), "r"(ROW_BYTES) : "memory");
        asm volatile("cp.async.bulk.shared::cta.global.mbarrier::complete_tx::bytes "
                     "[%0], [%1], %2, [%3];"
                     :: "r"(sb[j]), "l"(src), "r"(ROW_BYTES), "r"(m) : "memory");
    }

    for (int i = 0; i < ROWS_PER_CTA; i++) {
        const int s   = i & (STAGES - 1);
        const uint32_t par = (i / STAGES) & 1;

        // wait for row i's data in buf[s]
        {
            uint32_t done;
            asm volatile(
                "{\n\t.reg .pred p;\n\t"
                "mbarrier.try_wait.parity.acquire.cta.shared::cta.b64 p, [%1], %2;\n\t"
                "selp.b32 %0, 1, 0, p;\n\t}"
                : "=r"(done) : "r"(mb[s]), "r"(par) : "memory");
            if (!done) {
                asm volatile(
                    "{\n\t.reg .pred P1;\n\t"
                    "W%=:\n\t"
                    "mbarrier.try_wait.parity.acquire.cta.shared::cta.b64 P1, [%0], %1, 0x989680;\n\t"
                    "@P1 bra.uni E%=;\n\t"
                    "bra.uni W%=;\n\t"
                    "E%=:\n\t}"
                    :: "r"(mb[s]), "r"(par) : "memory");
            }
        }

        // store row i: smem -> global, 4KB burst
        {
            char* dst = (char*)out + (size_t)(row0 + i) * ROW_BYTES;
            asm volatile("cp.async.bulk.global.shared::cta.bulk_group [%0], [%1], %2;"
                         :: "l"(dst), "r"(sb[s]), "r"(ROW_BYTES) : "memory");
            asm volatile("cp.async.bulk.commit_group;" ::: "memory");
        }

        // issue load for row i+LOOKAHEAD into stage (i+LOOKAHEAD)%STAGES.
        // That stage's previous store was row i-2; wait_group.read 2 ensures
        // its SMEM read has completed (at most 2 store-groups pending).
        const int j = i + LOOKAHEAD;
        if (j < ROWS_PER_CTA) {
            asm volatile("cp.async.bulk.wait_group.read 2;" ::: "memory");
            const int sj = j & (STAGES - 1);
            int idx = ids[row0 + j];
            const char* src = (const char*)weight + (size_t)idx * ROW_BYTES;
            uint32_t m = mb[sj];
            asm volatile("mbarrier.arrive.expect_tx.shared.b64 _, [%0], %1;"
                         :: "r"(m), "r"(ROW_BYTES) : "memory");
            asm volatile("cp.async.bulk.shared::cta.global.mbarrier::complete_tx::bytes "
                         "[%0], [%1], %2, [%3];"
                         :: "r"(sb[sj]), "l"(src), "r"(ROW_BYTES), "r"(m) : "memory");
        }
    }
    // outstanding bulk stores complete before kernel completion (async proxy
    // drains at kernel end); no explicit final wait needed for correctness.
}

extern "C" void kernel_launch(void* const* d_in, const int* in_sizes, int n_in,
                              void* d_out, int out_size)
{
    // Identify inputs by element count:
    //   weight: 50257*1024 = 51463168 elements; ids: 32768 elements
    const float* weight;
    const int* ids;
    int n_rows;

    if (in_sizes[0] > in_sizes[1]) {
        weight = (const float*)d_in[0];
        ids    = (const int*)d_in[1];
        n_rows = in_sizes[1];
    } else {
        weight = (const float*)d_in[1];
        ids    = (const int*)d_in[0];
        n_rows = in_sizes[0];
    }

    int n_blocks = n_rows / ROWS_PER_CTA;  // 32768/32 = 1024, exact
    embed_bulk_kernel<<<n_blocks, 32>>>(weight, ids, (float*)d_out, n_rows);
}